// round 17
// baseline (speedup 1.0000x reference)
#include <cuda_runtime.h>
#include <math.h>

#define HW        4096          // H*W
#define CC        3             // channels
#define FF        64            // freq bins
#define BB        32            // batch
#define NSLAB     (BB*CC*FF)    // 6144 (b,c,f) slabs
#define NUM_KEEP  32
#define NKEPT     (NSLAB/2)     // exactly half kept (NUM_KEEP = FF/2)
#define BN_EPS    1e-5f
#define STHREADS  (CC*FF)       // 192 score threads

// Scratch (no device allocation allowed -> __device__ globals)
__device__ float g_pooled[NSLAB];
__device__ int   g_dropped[NKEPT];   // compacted dropped slab indices

// Write-through 16B store (R13: phase 1 at 44.0us with these).
__device__ __forceinline__ void stwt4(float4* p, float4 v) {
    asm volatile("st.global.wt.v4.f32 [%0], {%1,%2,%3,%4};"
                 :: "l"(p), "f"(v.x), "f"(v.y), "f"(v.z), "f"(v.w)
                 : "memory");
}

// ---------------------------------------------------------------------------
// Phase 1 (fused, R13-measured 44.0us = 200MB write cap, 100MB read hidden):
//   - 8 front-batched float4 loads of x (2 slabs per block)
//   - 8 independent zero stores to out2 (issue during load latency)
//   - 8 dependent copy stores x -> out1 (unconditional; dropped slabs get
//     re-zeroed by phase 3)
//   - pool reduction
// ---------------------------------------------------------------------------
__global__ void pool_copy_kernel(const float* __restrict__ x,
                                 float* __restrict__ out1,
                                 float* __restrict__ out2) {
    const int blk = blockIdx.x;          // slabs 2*blk, 2*blk+1
    const int t = threadIdx.x;           // 0..255
    const size_t base = (size_t)blk * (2 * HW / 4);
    const float4* __restrict__ p  = reinterpret_cast<const float4*>(x) + base;
    float4* __restrict__ o1 = reinterpret_cast<float4*>(out1) + base;
    float4* __restrict__ o2 = reinterpret_cast<float4*>(out2) + base;

    float4 v[8];
#pragma unroll
    for (int i = 0; i < 8; i++)
        v[i] = p[t + i * 256];

    // Independent zero stores: no scoreboard wait, fill the write pipe now.
    const float4 z = make_float4(0.f, 0.f, 0.f, 0.f);
#pragma unroll
    for (int i = 0; i < 8; i++)
        stwt4(o2 + t + i * 256, z);

    // Dependent copy stores, consume loads as they land.
#pragma unroll
    for (int i = 0; i < 8; i++)
        stwt4(o1 + t + i * 256, v[i]);

    float s0 = 0.f, s1 = 0.f;
#pragma unroll
    for (int i = 0; i < 4; i++)
        s0 += (v[i].x + v[i].y) + (v[i].z + v[i].w);
#pragma unroll
    for (int i = 4; i < 8; i++)
        s1 += (v[i].x + v[i].y) + (v[i].z + v[i].w);

#pragma unroll
    for (int o = 16; o > 0; o >>= 1) {
        s0 += __shfl_xor_sync(0xffffffffu, s0, o);
        s1 += __shfl_xor_sync(0xffffffffu, s1, o);
    }

    __shared__ float ws0[8], ws1[8];
    if ((t & 31) == 0) { ws0[t >> 5] = s0; ws1[t >> 5] = s1; }
    __syncthreads();
    if (t == 0) {
        float a = 0.f, b = 0.f;
#pragma unroll
        for (int i = 0; i < 8; i++) { a += ws0[i]; b += ws1[i]; }
        g_pooled[2 * blk]     = a * (1.0f / HW);
        g_pooled[2 * blk + 1] = b * (1.0f / HW);
    }
}

// ---------------------------------------------------------------------------
// Phase 2 (fast, R16 shape): scoring + top-32; 192 threads = one (c,g) pair.
// Weights staged in smem transposed. Emits compacted dropped-slab list
// (stable rank is a permutation -> perfect partition, no atomics).
// ---------------------------------------------------------------------------
__device__ __forceinline__ float sigmoidf(float v) {
    return 1.0f / (1.0f + expf(-v));
}

__global__ void __launch_bounds__(STHREADS)
score_kernel(const float* __restrict__ conv_w,
             const float* __restrict__ conv_b,
             const float* __restrict__ fc_w,
             const float* __restrict__ fc_b,
             const float* __restrict__ conv1_w,
             const float* __restrict__ conv1_b,
             const float* __restrict__ convr_w,
             const float* __restrict__ convr_b,
             const float* __restrict__ convl_w,
             const float* __restrict__ convl_b,
             const float* __restrict__ bn_gamma,
             const float* __restrict__ bn_beta,
             const float* __restrict__ bn_mean,
             const float* __restrict__ bn_var,
             const float* __restrict__ a_ptr) {
    const int b   = blockIdx.x;
    const int tid = threadIdx.x;     // 0..191
    const int c   = tid / FF;        // 0..2
    const int g   = tid % FF;        // 0..63

    __shared__ float wT[FF][FF + 1]; // conv_w transposed: wT[f][g]
    __shared__ float fT[FF][FF + 1]; // fc_w transposed
    __shared__ float pooled[CC][FF];
    __shared__ float xconv[CC][FF];
    __shared__ float scores[CC][FF];
    __shared__ float fin[CC][FF];
    __shared__ float xrc[CC][2][8];
    __shared__ float xrc2[CC][2][8];
    __shared__ float ar[CC][8];
    __shared__ float al[CC][8];

    // Stage weights: coalesced global reads, transposed smem writes.
    for (int idx = tid; idx < FF * FF; idx += STHREADS) {
        const int row = idx >> 6, col = idx & 63;
        wT[col][row] = conv_w[idx];
        fT[col][row] = fc_w[idx];
    }
    pooled[c][g] = g_pooled[(b * CC + c) * FF + g];
    __syncthreads();

    // x_conv[c][g] = sum_f pooled[c][f] * conv_w[g][f] + conv_b[g]
    {
        float s = conv_b[g];
#pragma unroll
        for (int f = 0; f < FF; f++)
            s = fmaf(pooled[c][f], wT[f][g], s);
        xconv[c][g] = s;
    }
    __syncthreads();

    // scores[c][g] = sigmoid(sum_f xconv[c][f] * fc_w[g][f] + fc_b[g])
    {
        float s = fc_b[g];
#pragma unroll
        for (int f = 0; f < FF; f++)
            s = fmaf(xconv[c][f], fT[f][g], s);
        scores[c][g] = sigmoidf(s);
    }

    // row / col means of pooled viewed as 8x8
    if (tid < CC * 8) {
        const int cc = tid / 8, i = tid % 8;
        float r = 0.f, co = 0.f;
#pragma unroll
        for (int j = 0; j < 8; j++) {
            r  += pooled[cc][i * 8 + j];
            co += pooled[cc][j * 8 + i];
        }
        xrc[cc][0][i] = r * 0.125f;
        xrc[cc][1][i] = co * 0.125f;
    }
    __syncthreads();

    // conv1 (mixes channels) + BN + sigmoid
    if (tid < CC * 8) {
        const int d = tid / 8, i = tid % 8;
        const float inv = rsqrtf(bn_var[d] + BN_EPS);
#pragma unroll
        for (int s2 = 0; s2 < 2; s2++) {
            float v = conv1_b[d];
#pragma unroll
            for (int cc = 0; cc < CC; cc++)
                v = fmaf(xrc[cc][s2][i], conv1_w[d * CC + cc], v);
            v = (v - bn_mean[d]) * inv;
            v = v * bn_gamma[d] + bn_beta[d];
            xrc2[d][s2][i] = sigmoidf(v);
        }
    }
    __syncthreads();

    // a_r, a_l (channel-mixing 1x1 convs + sigmoid)
    if (tid < CC * 8) {
        const int d = tid / 8, i = tid % 8;
        float vr = convr_b[d], vl = convl_b[d];
#pragma unroll
        for (int cc = 0; cc < CC; cc++) {
            vr = fmaf(xrc2[cc][0][i], convr_w[d * CC + cc], vr);
            vl = fmaf(xrc2[cc][1][i], convl_w[d * CC + cc], vl);
        }
        ar[d][i] = sigmoidf(vr);
        al[d][i] = sigmoidf(vl);
    }
    __syncthreads();

    // final = a * (a_r outer a_l) + (1-a) * scores
    {
        const float a = *a_ptr;
        const int i = g >> 3, j = g & 7;
        fin[c][g] = a * ar[c][i] * al[c][j] + (1.0f - a) * scores[c][g];
    }
    __syncthreads();

    // Stable rank (ties -> lower index, matches jax top_k). Emit dropped.
    {
        const float v = fin[c][g];
        int rank = 0;
#pragma unroll
        for (int f = 0; f < FF; f++) {
            const float u = fin[c][f];
            rank += (u > v) || (u == v && f < g);
        }
        const int row = b * CC + c;
        if (rank >= NUM_KEEP)
            g_dropped[row * NUM_KEEP + (rank - NUM_KEEP)] = row * FF + g;
    }
}

// ---------------------------------------------------------------------------
// Phase 3: re-zero the dropped slabs of out1 via the compacted list.
// Dense pure-store kernel: every block zeroes 2 dropped slabs (32KB), no
// loads, no dead blocks. ~10us (R13 accounting, de-confounded from score).
// ---------------------------------------------------------------------------
__global__ void zero_dropped_kernel(float* __restrict__ out1) {
    const int blk = blockIdx.x;          // 0..NKEPT/2-1
    const int t = threadIdx.x;           // 0..255

    const int ds0 = g_dropped[2 * blk];
    const int ds1 = g_dropped[2 * blk + 1];

    float4* __restrict__ o = reinterpret_cast<float4*>(out1);
    const size_t b0 = (size_t)ds0 * (HW / 4) + t;
    const size_t b1 = (size_t)ds1 * (HW / 4) + t;

    const float4 z = make_float4(0.f, 0.f, 0.f, 0.f);
#pragma unroll
    for (int i = 0; i < 4; i++) stwt4(o + b0 + i * 256, z);
#pragma unroll
    for (int i = 0; i < 4; i++) stwt4(o + b1 + i * 256, z);
}

// ---------------------------------------------------------------------------
extern "C" void kernel_launch(void* const* d_in, const int* in_sizes, int n_in,
                              void* d_out, int out_size) {
    const float* x_freq  = (const float*)d_in[0];
    const float* conv_w  = (const float*)d_in[1];
    const float* conv_b  = (const float*)d_in[2];
    const float* fc_w    = (const float*)d_in[3];
    const float* fc_b    = (const float*)d_in[4];
    const float* conv1_w = (const float*)d_in[5];
    const float* conv1_b = (const float*)d_in[6];
    const float* convr_w = (const float*)d_in[7];
    const float* convr_b = (const float*)d_in[8];
    const float* convl_w = (const float*)d_in[9];
    const float* convl_b = (const float*)d_in[10];
    const float* bn_gamma = (const float*)d_in[11];
    const float* bn_beta  = (const float*)d_in[12];
    const float* bn_mean  = (const float*)d_in[13];
    const float* bn_var   = (const float*)d_in[14];
    const float* a_scalar = (const float*)d_in[15];

    float* out1 = (float*)d_out;                       // x_pruned
    float* out2 = (float*)d_out + (size_t)NSLAB * HW;  // x_pruned_2k (zeros)

    pool_copy_kernel<<<NSLAB / 2, 256>>>(x_freq, out1, out2);
    score_kernel<<<BB, STHREADS>>>(conv_w, conv_b, fc_w, fc_b,
                                   conv1_w, conv1_b, convr_w, convr_b,
                                   convl_w, convl_b,
                                   bn_gamma, bn_beta, bn_mean, bn_var,
                                   a_scalar);
    zero_dropped_kernel<<<NKEPT / 2, 256>>>(out1);
}